// round 15
// baseline (speedup 1.0000x reference)
#include <cuda_runtime.h>
#include <cuda_fp16.h>
#include <math.h>
#include <stdint.h>

// ---------------------------------------------------------------------------
// LSTMDecoder via mma.sync fp16 single-pass (tcgen05 unavailable: harness
// targets compute_103 without the 'a' suffix).
//
// lstm_mma: 128 persistent CTAs x 512 threads. Per CTA: 8 hidden units
// (32 gate rows x 64 batch). W_hh fp16 slice resident in SMEM (64.5KB) all
// steps. Per step: 4 K-chunks (256 kk) of single-plane fp16 h streamed via
// cp.async double buffer; 16 warps = kw(4) x mi(2) x nj(2); single-pass
// W*h m16n8k16 fp16 with fp32 accum; 4-way cross-kw reduce in SMEM;
// unit-fastest epilogue with gathers; split-counter barrier.
// R15 vs R14: (a) drop Wlo pass (fp16 W single plane; error budget verified:
// measured 3.0e-5 with h-only rounding -> ~sqrt(2)x with W rounding),
// (b) 4 chunks of 256 kk (half the sync/wait rounds), funded by the halved
// W image.
// ---------------------------------------------------------------------------

#define Bz    64
#define Hh    1024
#define Ll    128
#define G4    4096
#define KDIM  512
#define NCTA  128
#define TPB   512

__device__ float g_rp[256 * 4096];
__device__ float g_tp[256 * 4096];
__device__ float g_xp[64 * 4096];
__device__ __align__(16) unsigned char g_wimg[128u * 66048u];      // fp16 W
__device__ __align__(16) unsigned short g_h16[2][65536];           // fp16 h
__device__ unsigned int g_ctr8[256];   // 8 counters at stride 32 (128B apart)
__device__ int          g_is64;

// ---- smem layout (bytes, dynamic) ----
#define OFF_WHI 0
#define OFF_HB0 66048
#define OFF_HB1 99840
#define SMEM_BYTES 133632
#define W_STRIDE 2064       // 1024 fp16 * 2B + 16 pad
#define H_STRIDE 528        // 256 fp16 * 2B + 16 pad

// ---- helpers ---------------------------------------------------------------
__device__ __forceinline__ uint32_t smem_to_u32(const void* smem_ptr) {
    uint32_t addr;
    asm("{ .reg .u64 tmp; cvta.to.shared.u64 tmp, %1; cvt.u32.u64 %0, tmp; }"
        : "=r"(addr) : "l"(smem_ptr));
    return addr;
}

#define CP_ASYNC16(dst, src) \
    asm volatile("cp.async.cg.shared.global [%0], [%1], 16;" \
                 :: "r"((uint32_t)(dst)), "l"(src) : "memory")
#define CP_COMMIT() \
    asm volatile("cp.async.commit_group;" ::: "memory")
#define CP_WAIT0() \
    asm volatile("cp.async.wait_group 0;" ::: "memory")

__device__ __forceinline__ void ldsm4(uint32_t& r0, uint32_t& r1,
                                      uint32_t& r2, uint32_t& r3,
                                      uint32_t addr) {
    asm volatile(
        "ldmatrix.sync.aligned.m8n8.x4.shared.b16 {%0, %1, %2, %3}, [%4];"
        : "=r"(r0), "=r"(r1), "=r"(r2), "=r"(r3)
        : "r"(addr));
}

__device__ __forceinline__ void mma_f16(float& d0, float& d1, float& d2, float& d3,
                                        uint32_t a0, uint32_t a1, uint32_t a2, uint32_t a3,
                                        uint32_t b0, uint32_t b1) {
    asm volatile(
        "mma.sync.aligned.m16n8k16.row.col.f32.f16.f16.f32 "
        "{%0, %1, %2, %3}, {%4, %5, %6, %7}, {%8, %9}, {%0, %1, %2, %3};"
        : "+f"(d0), "+f"(d1), "+f"(d2), "+f"(d3)
        : "r"(a0), "r"(a1), "r"(a2), "r"(a3), "r"(b0), "r"(b1));
}

__device__ __forceinline__ unsigned short hbits(float v) {
    __half t = __float2half_rn(v);
    return *(unsigned short*)&t;
}
__device__ __forceinline__ float sigf(float x) {
    return 1.0f / (1.0f + __expf(-x));
}

// ---------------------------------------------------------------------------
// fused_proj: tables + counter reset + pa dtype sniff. grid (64,4,3), blk 256.
// ---------------------------------------------------------------------------
__global__ void fused_proj(const float* __restrict__ rule,
                           const float* __restrict__ toke,
                           const float* __restrict__ x,
                           const float* __restrict__ Wih,
                           const float* __restrict__ b1,
                           const float* __restrict__ b2,
                           const int*   __restrict__ pa32)
{
    const int z = blockIdx.z;
    const float* E;
    float* Out;
    int M;
    int colOff;
    int addBias = 0;
    if (z == 0)      { E = rule; Out = g_rp; M = 256; colOff = 512; }
    else if (z == 1) { E = toke; Out = g_tp; M = 256; colOff = 512; }
    else             { E = x;    Out = g_xp; M = 64;  colOff = 0; addBias = 1; }

    if (z == 2 && blockIdx.x == 0 && blockIdx.y == 0) {
        __shared__ int any_nz;
        if (threadIdx.x == 0) { any_nz = 0; }
        if (threadIdx.x < 8) g_ctr8[threadIdx.x * 32] = 0u;
        __syncthreads();
        if (threadIdx.x < 256 && pa32[threadIdx.x * 2 + 1] != 0)
            atomicAdd(&any_nz, 1);
        __syncthreads();
        if (threadIdx.x == 0) g_is64 = (any_nz == 0) ? 1 : 0;
    }
    if (blockIdx.y * 64 >= M) return;

    __shared__ float Es[64][17];
    __shared__ float Ws[64][17];

    const int i0 = blockIdx.y * 64;
    const int j0 = blockIdx.x * 64;
    const int t  = threadIdx.x;
    const int ty = t >> 4;
    const int tx = t & 15;

    float acc[4][4];
#pragma unroll
    for (int i = 0; i < 4; i++)
#pragma unroll
        for (int j = 0; j < 4; j++) acc[i][j] = 0.f;

    const int ii = t >> 2;
    const int a4 = (t & 3) * 4;

    for (int a0 = 0; a0 < KDIM; a0 += 16) {
        float4 ev = make_float4(0.f, 0.f, 0.f, 0.f);
        if (i0 + ii < M)
            ev = *(const float4*)(E + (size_t)(i0 + ii) * KDIM + a0 + a4);
        Es[ii][a4 + 0] = ev.x;
        Es[ii][a4 + 1] = ev.y;
        Es[ii][a4 + 2] = ev.z;
        Es[ii][a4 + 3] = ev.w;

        float4 wv = *(const float4*)(Wih + (size_t)(j0 + ii) * 1024 + colOff + a0 + a4);
        Ws[ii][a4 + 0] = wv.x;
        Ws[ii][a4 + 1] = wv.y;
        Ws[ii][a4 + 2] = wv.z;
        Ws[ii][a4 + 3] = wv.w;
        __syncthreads();

#pragma unroll
        for (int aa = 0; aa < 16; aa++) {
            float av[4];
            float bv[4];
#pragma unroll
            for (int r2 = 0; r2 < 4; r2++) av[r2] = Es[ty * 4 + r2][aa];
#pragma unroll
            for (int r2 = 0; r2 < 4; r2++) bv[r2] = Ws[tx * 4 + r2][aa];
#pragma unroll
            for (int i = 0; i < 4; i++)
#pragma unroll
                for (int j = 0; j < 4; j++) acc[i][j] = fmaf(av[i], bv[j], acc[i][j]);
        }
        __syncthreads();
    }

#pragma unroll
    for (int i = 0; i < 4; i++) {
        int gi = i0 + ty * 4 + i;
        if (gi >= M) continue;
#pragma unroll
        for (int j = 0; j < 4; j++) {
            int gj = j0 + tx * 4 + j;
            float v = acc[i][j];
            if (addBias) v += b1[gj] + b2[gj];
            Out[(size_t)gi * G4 + gj] = v;
        }
    }
}

// ---------------------------------------------------------------------------
// prep_w: bake W_hh into per-CTA fp16 images (SMEM layout, stride 2064).
// ---------------------------------------------------------------------------
__global__ void prep_w(const float* __restrict__ Whh)
{
    const int id   = blockIdx.x * 256 + threadIdx.x;
    const int g    = id >> 10;
    const int r    = (id >> 5) & 31;
    const int kseg = id & 31;
    const int k0   = kseg * 32;
    const int gate = r >> 3;
    const int u    = r & 7;

    const float* src = Whh + (size_t)(gate * 1024 + g * 8 + u) * 1024 + k0;
    unsigned char* dhi = g_wimg + (size_t)g * 66048 + r * W_STRIDE + k0 * 2;

#pragma unroll
    for (int j = 0; j < 4; j++) {
        float4 va = *(const float4*)(src + j * 8);
        float4 vb = *(const float4*)(src + j * 8 + 4);
        float v[8];
        v[0] = va.x; v[1] = va.y; v[2] = va.z; v[3] = va.w;
        v[4] = vb.x; v[5] = vb.y; v[6] = vb.z; v[7] = vb.w;
        unsigned int hw[4];
#pragma unroll
        for (int q = 0; q < 4; q++) {
            hw[q] = (unsigned)hbits(v[2 * q]) | ((unsigned)hbits(v[2 * q + 1]) << 16);
        }
        *(uint4*)(dhi + j * 16) = make_uint4(hw[0], hw[1], hw[2], hw[3]);
    }
}

// ---------------------------------------------------------------------------
// prep_h0: bake initial h into g_h16 parity 0 (single fp16 plane).
// ---------------------------------------------------------------------------
__global__ void prep_h0(const float* __restrict__ h0)
{
    const int id = blockIdx.x * 256 + threadIdx.x;
    if (id >= 2048) return;
    const int b    = id >> 5;
    const int kseg = id & 31;
    const int k0   = kseg * 32;

    const float* src = h0 + (size_t)b * 1024 + k0;
    unsigned short* dhi = &g_h16[0][b * 1024 + k0];

#pragma unroll
    for (int j = 0; j < 4; j++) {
        float4 va = *(const float4*)(src + j * 8);
        float4 vb = *(const float4*)(src + j * 8 + 4);
        float v[8];
        v[0] = va.x; v[1] = va.y; v[2] = va.z; v[3] = va.w;
        v[4] = vb.x; v[5] = vb.y; v[6] = vb.z; v[7] = vb.w;
        unsigned int hw[4];
#pragma unroll
        for (int q = 0; q < 4; q++) {
            hw[q] = (unsigned)hbits(v[2 * q]) | ((unsigned)hbits(v[2 * q + 1]) << 16);
        }
        *(uint4*)(dhi + j * 8) = make_uint4(hw[0], hw[1], hw[2], hw[3]);
    }
}

// ---------------------------------------------------------------------------
// lstm_mma: persistent 128-CTA x 512-thread mma.sync recurrence.
// ---------------------------------------------------------------------------
__global__ void __launch_bounds__(TPB, 1)
lstm_mma(const float* __restrict__ c0,
         const void*  __restrict__ pa_raw,
         const float* __restrict__ tok_embed,
         const float* __restrict__ W_ih,
         float* __restrict__ out)
{
    extern __shared__ unsigned char smem[];
    const uint32_t sb = smem_to_u32(smem);
    const int tid  = threadIdx.x;
    const int wid  = tid >> 5;
    const int lane = tid & 31;
    const int g    = blockIdx.x;
    const int is64 = g_is64;

    // ---- one-time W image copy into SMEM (66048 B) ----
    {
        const unsigned char* wsrc = g_wimg + (size_t)g * 66048;
        for (int i = tid; i < 4128; i += TPB) {
            CP_ASYNC16(sb + OFF_WHI + i * 16, wsrc + (size_t)i * 16);
        }
        CP_COMMIT();
        CP_WAIT0();
        __syncthreads();
    }

    // ---- epilogue identity: 1 (b, u) pair per thread, unit-fastest ----
    const int u_e = tid & 7;
    const int b_e = tid >> 3;          // 0..63
    const int kg  = g * 8 + u_e;
    float cst = c0[(size_t)b_e * Hh + kg];
    float hst = 0.f;

    // ---- GEMM identity: 16 warps = kw(4) x mi(2) x nj(2) ----
    const int kw = wid >> 2;           // 0..3  (64 kk each within a 256 chunk)
    const int mi = (wid >> 1) & 1;     // 0..1  (16 gate rows)
    const int nj = wid & 1;            // 0..1  (32 batches)
    const uint32_t aoff = (uint32_t)((mi * 16 + (lane & 15)) * W_STRIDE
                                     + ((lane & 16) ? 16 : 0));
    const uint32_t boff = (uint32_t)((nj * 32 + (lane & 15)) * H_STRIDE
                                     + ((lane & 16) ? 16 : 0));

    // staging identity: row = tid>>3 (0..63), seg = tid&7 (32 kk = 64B each)
    const int sg_row = tid >> 3;
    const int sg_seg = tid & 7;

    float* smemD = (float*)(smem + OFF_HB0);   // [kw 4][32][65] fp32 overlay

#pragma unroll 1
    for (int l = 0; l < Ll; l++) {
        const unsigned short* hsrc = &g_h16[l & 1][0];

        // prologue: issue chunk 0 (256 kk) into HB0
        {
            const unsigned short* srcH = hsrc + sg_row * 1024 + sg_seg * 32;
            const uint32_t dstH = sb + OFF_HB0 + sg_row * H_STRIDE + sg_seg * 64;
            CP_ASYNC16(dstH,      srcH);
            CP_ASYNC16(dstH + 16, srcH + 8);
            CP_ASYNC16(dstH + 32, srcH + 16);
            CP_ASYNC16(dstH + 48, srcH + 24);
            CP_COMMIT();
        }

        float acc[16];
#pragma unroll
        for (int i = 0; i < 16; i++) acc[i] = 0.f;

#pragma unroll 1
        for (int c = 0; c < 4; c++) {
            CP_WAIT0();
            __syncthreads();
            if (c < 3) {
                const unsigned short* srcH = hsrc + sg_row * 1024 + (c + 1) * 256 + sg_seg * 32;
                const uint32_t hb = (c & 1) ? OFF_HB0 : OFF_HB1;
                const uint32_t dstH = sb + hb + sg_row * H_STRIDE + sg_seg * 64;
                CP_ASYNC16(dstH,      srcH);
                CP_ASYNC16(dstH + 16, srcH + 8);
                CP_ASYNC16(dstH + 32, srcH + 16);
                CP_ASYNC16(dstH + 48, srcH + 24);
                CP_COMMIT();
            }

            const uint32_t hb   = (c & 1) ? OFF_HB1 : OFF_HB0;
            const uint32_t bHi  = sb + hb + boff + kw * 128;
            const uint32_t aHiB = sb + OFF_WHI + aoff + c * 512 + kw * 128;

#pragma unroll
            for (int ks = 0; ks < 4; ks++) {
                uint32_t ah0, ah1, ah2, ah3;
                uint32_t bh0, bh1, bh2, bh3, bh4, bh5, bh6, bh7;
                ldsm4(ah0, ah1, ah2, ah3, aHiB + ks * 32);
                ldsm4(bh0, bh1, bh2, bh3, bHi + ks * 32);
                ldsm4(bh4, bh5, bh6, bh7, bHi + 16 * H_STRIDE + ks * 32);
                mma_f16(acc[0],  acc[1],  acc[2],  acc[3],  ah0, ah1, ah2, ah3, bh0, bh2);
                mma_f16(acc[4],  acc[5],  acc[6],  acc[7],  ah0, ah1, ah2, ah3, bh1, bh3);
                mma_f16(acc[8],  acc[9],  acc[10], acc[11], ah0, ah1, ah2, ah3, bh4, bh6);
                mma_f16(acc[12], acc[13], acc[14], acc[15], ah0, ah1, ah2, ah3, bh5, bh7);
            }
        }
        __syncthreads();   // computes done; HB0/HB1 free for D overlay

        // ---- write D fragments to smemD[kw][32][65] ----
        {
            const int lr = lane >> 2;
            const int lc = (lane & 3) * 2;
            const int row0 = mi * 16 + lr;
            float* dk = smemD + kw * 2080;
#pragma unroll
            for (int s = 0; s < 4; s++) {
                const int col = nj * 32 + s * 8 + lc;
                dk[row0 * 65 + col]           = acc[s * 4 + 0];
                dk[row0 * 65 + col + 1]       = acc[s * 4 + 1];
                dk[(row0 + 8) * 65 + col]     = acc[s * 4 + 2];
                dk[(row0 + 8) * 65 + col + 1] = acc[s * 4 + 3];
            }
        }
        __syncthreads();

        // ---- epilogue: 1 (b, u) pair per thread (unit-fastest) ----
        {
            unsigned short* hdst = &g_h16[(l + 1) & 1][0];
            const size_t pidx = ((size_t)l * Bz + b_e) * 3;
            long long ridx;
            long long tidx;
            if (is64) {
                const long long* pp = (const long long*)pa_raw;
                ridx = pp[pidx];
                tidx = pp[pidx + 1];
            } else {
                const int* pp = (const int*)pa_raw;
                ridx = (long long)pp[pidx];
                tidx = (long long)pp[pidx + 1];
            }
            float gv[4];
#pragma unroll
            for (int gt = 0; gt < 4; gt++) {
                const int row = gt * 8 + u_e;
                float pre = smemD[row * 65 + b_e]
                          + smemD[2080 + row * 65 + b_e]
                          + smemD[4160 + row * 65 + b_e]
                          + smemD[6240 + row * 65 + b_e];
                const int gidx = gt * 1024 + kg;
                float xgv = g_xp[(size_t)b_e * G4 + gidx];
                if (ridx >= 0 && ridx < 256) {
                    xgv += g_rp[(size_t)ridx * G4 + gidx];
                }
                if (tidx >= 0 && tidx < 256) {
                    xgv += g_tp[(size_t)tidx * G4 + gidx];
                } else if (tidx >= 256 && tidx < 32000) {
                    const float* te = tok_embed + (size_t)tidx * KDIM;
                    const float* wa = W_ih + (size_t)gidx * 1024 + 512;
                    float d = 0.f;
                    for (int a = 0; a < KDIM; a++) {
                        d = fmaf(te[a], wa[a], d);
                    }
                    xgv += d;
                }
                gv[gt] = pre + xgv;
            }
            const float c1 = sigf(gv[1]) * cst + sigf(gv[0]) * tanhf(gv[2]);
            const float h1 = sigf(gv[3]) * tanhf(c1);
            cst = c1;
            hst = h1;
            out[((size_t)l * Bz + b_e) * Hh + kg] = h1;

            hdst[b_e * 1024 + kg] = hbits(h1);
        }

        // ---- device-wide barrier: 8 split counters, 16 arrivals each ----
        __threadfence();
        __syncthreads();
        if (tid == 0) {
            atomicAdd(&g_ctr8[(g & 7) * 32], 1u);
        }
        if (tid < 8) {
            const unsigned tgt = (unsigned)(l + 1) * 16u;
            while (*(volatile unsigned int*)&g_ctr8[tid * 32] < tgt) {
                __nanosleep(32);
            }
        }
        __syncthreads();
    }

    // ---- final h_n, c_n ----
    {
        const size_t base_hn = (size_t)Ll * Bz * Hh;
        const size_t base_cn = base_hn + (size_t)Bz * Hh;
        out[base_hn + (size_t)b_e * Hh + kg] = hst;
        out[base_cn + (size_t)b_e * Hh + kg] = cst;
    }
}

// ---------------------------------------------------------------------------
extern "C" void kernel_launch(void* const* d_in, const int* in_sizes, int n_in,
                              void* d_out, int out_size)
{
    const float* x    = (const float*)d_in[0];
    const void*  pa   = (const void*)d_in[1];
    // d_in[2] = mask (unused by the reference computation)
    const float* h0   = (const float*)d_in[3];
    const float* c0   = (const float*)d_in[4];
    const float* rule = (const float*)d_in[5];
    const float* toke = (const float*)d_in[6];
    const float* Wih  = (const float*)d_in[7];
    const float* Whh  = (const float*)d_in[8];
    const float* bih  = (const float*)d_in[9];
    const float* bhh  = (const float*)d_in[10];
    float* out = (float*)d_out;

    fused_proj<<<dim3(64, 4, 3), 256>>>(rule, toke, x, Wih, bih, bhh,
                                        (const int*)pa);
    prep_w<<<512, 256>>>(Whh);
    prep_h0<<<8, 256>>>(h0);

    cudaFuncSetAttribute(lstm_mma,
                         cudaFuncAttributeMaxDynamicSharedMemorySize,
                         SMEM_BYTES);
    lstm_mma<<<NCTA, TPB, SMEM_BYTES>>>(c0, pa, toke, Wih, out);
}

// round 16
// speedup vs baseline: 1.0104x; 1.0104x over previous
#include <cuda_runtime.h>
#include <cuda_fp16.h>
#include <math.h>
#include <stdint.h>

// ---------------------------------------------------------------------------
// LSTMDecoder via mma.sync fp16 single-pass (tcgen05 unavailable: harness
// targets compute_103 without the 'a' suffix).
//
// lstm_mma: 128 persistent CTAs x 512 threads. Per CTA: 8 hidden units
// (32 gate rows x 64 batch). W_hh fp16 slice resident in SMEM (64.5KB).
// Per step: 8 K-chunks (128 kk, R14 pipeline) of single-plane fp16 h via
// cp.async double buffer; 16 warps = kw(4) x mi(2) x nj(2); single-pass
// W*h m16n8k16 fp16, fp32 accum; 4-way cross-kw reduce in SMEM;
// unit-fastest epilogue with gathers; split-counter barrier with
// release-arrival by thread 0 (no per-thread gpu fences).
// R16 vs R14: drop Wlo pass (keep 8x128 chunking); CG-style barrier arrival.
// ---------------------------------------------------------------------------

#define Bz    64
#define Hh    1024
#define Ll    128
#define G4    4096
#define KDIM  512
#define NCTA  128
#define TPB   512

__device__ float g_rp[256 * 4096];
__device__ float g_tp[256 * 4096];
__device__ float g_xp[64 * 4096];
__device__ __align__(16) unsigned char g_wimg[128u * 66048u];      // fp16 W
__device__ __align__(16) unsigned short g_h16[2][65536];           // fp16 h
__device__ unsigned int g_ctr8[256];   // 8 counters at stride 32 (128B apart)
__device__ int          g_is64;

// ---- smem layout (bytes, dynamic) ----
#define OFF_WHI 0
#define OFF_HB0 66048
#define OFF_HB1 83456
#define SMEM_BYTES 100864
#define W_STRIDE 2064       // 1024 fp16 * 2B + 16 pad
#define H_STRIDE 272        // 128 fp16 * 2B + 16 pad

// ---- helpers ---------------------------------------------------------------
__device__ __forceinline__ uint32_t smem_to_u32(const void* smem_ptr) {
    uint32_t addr;
    asm("{ .reg .u64 tmp; cvta.to.shared.u64 tmp, %1; cvt.u32.u64 %0, tmp; }"
        : "=r"(addr) : "l"(smem_ptr));
    return addr;
}

#define CP_ASYNC16(dst, src) \
    asm volatile("cp.async.cg.shared.global [%0], [%1], 16;" \
                 :: "r"((uint32_t)(dst)), "l"(src) : "memory")
#define CP_COMMIT() \
    asm volatile("cp.async.commit_group;" ::: "memory")
#define CP_WAIT0() \
    asm volatile("cp.async.wait_group 0;" ::: "memory")

__device__ __forceinline__ void ldsm4(uint32_t& r0, uint32_t& r1,
                                      uint32_t& r2, uint32_t& r3,
                                      uint32_t addr) {
    asm volatile(
        "ldmatrix.sync.aligned.m8n8.x4.shared.b16 {%0, %1, %2, %3}, [%4];"
        : "=r"(r0), "=r"(r1), "=r"(r2), "=r"(r3)
        : "r"(addr));
}

__device__ __forceinline__ void mma_f16(float& d0, float& d1, float& d2, float& d3,
                                        uint32_t a0, uint32_t a1, uint32_t a2, uint32_t a3,
                                        uint32_t b0, uint32_t b1) {
    asm volatile(
        "mma.sync.aligned.m16n8k16.row.col.f32.f16.f16.f32 "
        "{%0, %1, %2, %3}, {%4, %5, %6, %7}, {%8, %9}, {%0, %1, %2, %3};"
        : "+f"(d0), "+f"(d1), "+f"(d2), "+f"(d3)
        : "r"(a0), "r"(a1), "r"(a2), "r"(a3), "r"(b0), "r"(b1));
}

__device__ __forceinline__ void red_release(unsigned int* addr) {
    asm volatile("red.release.gpu.global.add.u32 [%0], 1;"
                 :: "l"(addr) : "memory");
}

__device__ __forceinline__ unsigned short hbits(float v) {
    __half t = __float2half_rn(v);
    return *(unsigned short*)&t;
}
__device__ __forceinline__ float sigf(float x) {
    return 1.0f / (1.0f + __expf(-x));
}

// ---------------------------------------------------------------------------
// fused_proj: tables + counter reset + pa dtype sniff. grid (64,4,3), blk 256.
// ---------------------------------------------------------------------------
__global__ void fused_proj(const float* __restrict__ rule,
                           const float* __restrict__ toke,
                           const float* __restrict__ x,
                           const float* __restrict__ Wih,
                           const float* __restrict__ b1,
                           const float* __restrict__ b2,
                           const int*   __restrict__ pa32)
{
    const int z = blockIdx.z;
    const float* E;
    float* Out;
    int M;
    int colOff;
    int addBias = 0;
    if (z == 0)      { E = rule; Out = g_rp; M = 256; colOff = 512; }
    else if (z == 1) { E = toke; Out = g_tp; M = 256; colOff = 512; }
    else             { E = x;    Out = g_xp; M = 64;  colOff = 0; addBias = 1; }

    if (z == 2 && blockIdx.x == 0 && blockIdx.y == 0) {
        __shared__ int any_nz;
        if (threadIdx.x == 0) { any_nz = 0; }
        if (threadIdx.x < 8) g_ctr8[threadIdx.x * 32] = 0u;
        __syncthreads();
        if (threadIdx.x < 256 && pa32[threadIdx.x * 2 + 1] != 0)
            atomicAdd(&any_nz, 1);
        __syncthreads();
        if (threadIdx.x == 0) g_is64 = (any_nz == 0) ? 1 : 0;
    }
    if (blockIdx.y * 64 >= M) return;

    __shared__ float Es[64][17];
    __shared__ float Ws[64][17];

    const int i0 = blockIdx.y * 64;
    const int j0 = blockIdx.x * 64;
    const int t  = threadIdx.x;
    const int ty = t >> 4;
    const int tx = t & 15;

    float acc[4][4];
#pragma unroll
    for (int i = 0; i < 4; i++)
#pragma unroll
        for (int j = 0; j < 4; j++) acc[i][j] = 0.f;

    const int ii = t >> 2;
    const int a4 = (t & 3) * 4;

    for (int a0 = 0; a0 < KDIM; a0 += 16) {
        float4 ev = make_float4(0.f, 0.f, 0.f, 0.f);
        if (i0 + ii < M)
            ev = *(const float4*)(E + (size_t)(i0 + ii) * KDIM + a0 + a4);
        Es[ii][a4 + 0] = ev.x;
        Es[ii][a4 + 1] = ev.y;
        Es[ii][a4 + 2] = ev.z;
        Es[ii][a4 + 3] = ev.w;

        float4 wv = *(const float4*)(Wih + (size_t)(j0 + ii) * 1024 + colOff + a0 + a4);
        Ws[ii][a4 + 0] = wv.x;
        Ws[ii][a4 + 1] = wv.y;
        Ws[ii][a4 + 2] = wv.z;
        Ws[ii][a4 + 3] = wv.w;
        __syncthreads();

#pragma unroll
        for (int aa = 0; aa < 16; aa++) {
            float av[4];
            float bv[4];
#pragma unroll
            for (int r2 = 0; r2 < 4; r2++) av[r2] = Es[ty * 4 + r2][aa];
#pragma unroll
            for (int r2 = 0; r2 < 4; r2++) bv[r2] = Ws[tx * 4 + r2][aa];
#pragma unroll
            for (int i = 0; i < 4; i++)
#pragma unroll
                for (int j = 0; j < 4; j++) acc[i][j] = fmaf(av[i], bv[j], acc[i][j]);
        }
        __syncthreads();
    }

#pragma unroll
    for (int i = 0; i < 4; i++) {
        int gi = i0 + ty * 4 + i;
        if (gi >= M) continue;
#pragma unroll
        for (int j = 0; j < 4; j++) {
            int gj = j0 + tx * 4 + j;
            float v = acc[i][j];
            if (addBias) v += b1[gj] + b2[gj];
            Out[(size_t)gi * G4 + gj] = v;
        }
    }
}

// ---------------------------------------------------------------------------
// prep_w: bake W_hh into per-CTA fp16 images (SMEM layout, stride 2064).
// ---------------------------------------------------------------------------
__global__ void prep_w(const float* __restrict__ Whh)
{
    const int id   = blockIdx.x * 256 + threadIdx.x;
    const int g    = id >> 10;
    const int r    = (id >> 5) & 31;
    const int kseg = id & 31;
    const int k0   = kseg * 32;
    const int gate = r >> 3;
    const int u    = r & 7;

    const float* src = Whh + (size_t)(gate * 1024 + g * 8 + u) * 1024 + k0;
    unsigned char* dhi = g_wimg + (size_t)g * 66048 + r * W_STRIDE + k0 * 2;

#pragma unroll
    for (int j = 0; j < 4; j++) {
        float4 va = *(const float4*)(src + j * 8);
        float4 vb = *(const float4*)(src + j * 8 + 4);
        float v[8];
        v[0] = va.x; v[1] = va.y; v[2] = va.z; v[3] = va.w;
        v[4] = vb.x; v[5] = vb.y; v[6] = vb.z; v[7] = vb.w;
        unsigned int hw[4];
#pragma unroll
        for (int q = 0; q < 4; q++) {
            hw[q] = (unsigned)hbits(v[2 * q]) | ((unsigned)hbits(v[2 * q + 1]) << 16);
        }
        *(uint4*)(dhi + j * 16) = make_uint4(hw[0], hw[1], hw[2], hw[3]);
    }
}

// ---------------------------------------------------------------------------
// prep_h0: bake initial h into g_h16 parity 0 (single fp16 plane).
// ---------------------------------------------------------------------------
__global__ void prep_h0(const float* __restrict__ h0)
{
    const int id = blockIdx.x * 256 + threadIdx.x;
    if (id >= 2048) return;
    const int b    = id >> 5;
    const int kseg = id & 31;
    const int k0   = kseg * 32;

    const float* src = h0 + (size_t)b * 1024 + k0;
    unsigned short* dhi = &g_h16[0][b * 1024 + k0];

#pragma unroll
    for (int j = 0; j < 4; j++) {
        float4 va = *(const float4*)(src + j * 8);
        float4 vb = *(const float4*)(src + j * 8 + 4);
        float v[8];
        v[0] = va.x; v[1] = va.y; v[2] = va.z; v[3] = va.w;
        v[4] = vb.x; v[5] = vb.y; v[6] = vb.z; v[7] = vb.w;
        unsigned int hw[4];
#pragma unroll
        for (int q = 0; q < 4; q++) {
            hw[q] = (unsigned)hbits(v[2 * q]) | ((unsigned)hbits(v[2 * q + 1]) << 16);
        }
        *(uint4*)(dhi + j * 8) = make_uint4(hw[0], hw[1], hw[2], hw[3]);
    }
}

// ---------------------------------------------------------------------------
// lstm_mma: persistent 128-CTA x 512-thread mma.sync recurrence.
// ---------------------------------------------------------------------------
__global__ void __launch_bounds__(TPB, 1)
lstm_mma(const float* __restrict__ c0,
         const void*  __restrict__ pa_raw,
         const float* __restrict__ tok_embed,
         const float* __restrict__ W_ih,
         float* __restrict__ out)
{
    extern __shared__ unsigned char smem[];
    const uint32_t sb = smem_to_u32(smem);
    const int tid  = threadIdx.x;
    const int wid  = tid >> 5;
    const int lane = tid & 31;
    const int g    = blockIdx.x;
    const int is64 = g_is64;

    // ---- one-time W image copy into SMEM (66048 B) ----
    {
        const unsigned char* wsrc = g_wimg + (size_t)g * 66048;
        for (int i = tid; i < 4128; i += TPB) {
            CP_ASYNC16(sb + OFF_WHI + i * 16, wsrc + (size_t)i * 16);
        }
        CP_COMMIT();
        CP_WAIT0();
        __syncthreads();
    }

    // ---- epilogue identity: 1 (b, u) pair per thread, unit-fastest ----
    const int u_e = tid & 7;
    const int b_e = tid >> 3;          // 0..63
    const int kg  = g * 8 + u_e;
    float cst = c0[(size_t)b_e * Hh + kg];
    float hst = 0.f;

    // ---- GEMM identity: 16 warps = kw(4) x mi(2) x nj(2) ----
    const int kw = wid >> 2;           // 0..3  (32 kk each within a 128 chunk)
    const int mi = (wid >> 1) & 1;     // 0..1  (16 gate rows)
    const int nj = wid & 1;            // 0..1  (32 batches)
    const uint32_t aoff = (uint32_t)((mi * 16 + (lane & 15)) * W_STRIDE
                                     + ((lane & 16) ? 16 : 0));
    const uint32_t boff = (uint32_t)((nj * 32 + (lane & 15)) * H_STRIDE
                                     + ((lane & 16) ? 16 : 0));

    // staging identity: row = tid>>3 (0..63), seg = tid&7 (16 kk = 32B each)
    const int sg_row = tid >> 3;
    const int sg_seg = tid & 7;

    float* smemD = (float*)(smem + OFF_HB0);   // [kw 4][32][65] fp32 overlay

#pragma unroll 1
    for (int l = 0; l < Ll; l++) {
        const unsigned short* hsrc = &g_h16[l & 1][0];

        // prologue: issue chunk 0 (128 kk) into HB0
        {
            const unsigned short* srcH = hsrc + sg_row * 1024 + sg_seg * 16;
            const uint32_t dstH = sb + OFF_HB0 + sg_row * H_STRIDE + sg_seg * 32;
            CP_ASYNC16(dstH,      srcH);
            CP_ASYNC16(dstH + 16, srcH + 8);
            CP_COMMIT();
        }

        float acc[16];
#pragma unroll
        for (int i = 0; i < 16; i++) acc[i] = 0.f;

#pragma unroll 1
        for (int c = 0; c < 8; c++) {
            CP_WAIT0();
            __syncthreads();
            if (c < 7) {
                const unsigned short* srcH = hsrc + sg_row * 1024 + (c + 1) * 128 + sg_seg * 16;
                const uint32_t hb = (c & 1) ? OFF_HB0 : OFF_HB1;
                const uint32_t dstH = sb + hb + sg_row * H_STRIDE + sg_seg * 32;
                CP_ASYNC16(dstH,      srcH);
                CP_ASYNC16(dstH + 16, srcH + 8);
                CP_COMMIT();
            }

            const uint32_t hb   = (c & 1) ? OFF_HB1 : OFF_HB0;
            const uint32_t bHi  = sb + hb + boff + kw * 64;
            const uint32_t aHiB = sb + OFF_WHI + aoff + c * 256 + kw * 64;

#pragma unroll
            for (int ks = 0; ks < 2; ks++) {
                uint32_t ah0, ah1, ah2, ah3;
                uint32_t bh0, bh1, bh2, bh3, bh4, bh5, bh6, bh7;
                ldsm4(ah0, ah1, ah2, ah3, aHiB + ks * 32);
                ldsm4(bh0, bh1, bh2, bh3, bHi + ks * 32);
                ldsm4(bh4, bh5, bh6, bh7, bHi + 16 * H_STRIDE + ks * 32);
                mma_f16(acc[0],  acc[1],  acc[2],  acc[3],  ah0, ah1, ah2, ah3, bh0, bh2);
                mma_f16(acc[4],  acc[5],  acc[6],  acc[7],  ah0, ah1, ah2, ah3, bh1, bh3);
                mma_f16(acc[8],  acc[9],  acc[10], acc[11], ah0, ah1, ah2, ah3, bh4, bh6);
                mma_f16(acc[12], acc[13], acc[14], acc[15], ah0, ah1, ah2, ah3, bh5, bh7);
            }
        }
        __syncthreads();   // computes done; HB0/HB1 free for D overlay

        // ---- write D fragments to smemD[kw][32][65] ----
        {
            const int lr = lane >> 2;
            const int lc = (lane & 3) * 2;
            const int row0 = mi * 16 + lr;
            float* dk = smemD + kw * 2080;
#pragma unroll
            for (int s = 0; s < 4; s++) {
                const int col = nj * 32 + s * 8 + lc;
                dk[row0 * 65 + col]           = acc[s * 4 + 0];
                dk[row0 * 65 + col + 1]       = acc[s * 4 + 1];
                dk[(row0 + 8) * 65 + col]     = acc[s * 4 + 2];
                dk[(row0 + 8) * 65 + col + 1] = acc[s * 4 + 3];
            }
        }
        __syncthreads();

        // ---- epilogue: 1 (b, u) pair per thread (unit-fastest) ----
        {
            unsigned short* hdst = &g_h16[(l + 1) & 1][0];
            const size_t pidx = ((size_t)l * Bz + b_e) * 3;
            long long ridx;
            long long tidx;
            if (is64) {
                const long long* pp = (const long long*)pa_raw;
                ridx = pp[pidx];
                tidx = pp[pidx + 1];
            } else {
                const int* pp = (const int*)pa_raw;
                ridx = (long long)pp[pidx];
                tidx = (long long)pp[pidx + 1];
            }
            float gv[4];
#pragma unroll
            for (int gt = 0; gt < 4; gt++) {
                const int row = gt * 8 + u_e;
                float pre = smemD[row * 65 + b_e]
                          + smemD[2080 + row * 65 + b_e]
                          + smemD[4160 + row * 65 + b_e]
                          + smemD[6240 + row * 65 + b_e];
                const int gidx = gt * 1024 + kg;
                float xgv = g_xp[(size_t)b_e * G4 + gidx];
                if (ridx >= 0 && ridx < 256) {
                    xgv += g_rp[(size_t)ridx * G4 + gidx];
                }
                if (tidx >= 0 && tidx < 256) {
                    xgv += g_tp[(size_t)tidx * G4 + gidx];
                } else if (tidx >= 256 && tidx < 32000) {
                    const float* te = tok_embed + (size_t)tidx * KDIM;
                    const float* wa = W_ih + (size_t)gidx * 1024 + 512;
                    float d = 0.f;
                    for (int a = 0; a < KDIM; a++) {
                        d = fmaf(te[a], wa[a], d);
                    }
                    xgv += d;
                }
                gv[gt] = pre + xgv;
            }
            const float c1 = sigf(gv[1]) * cst + sigf(gv[0]) * tanhf(gv[2]);
            const float h1 = sigf(gv[3]) * tanhf(c1);
            cst = c1;
            hst = h1;
            out[((size_t)l * Bz + b_e) * Hh + kg] = h1;

            hdst[b_e * 1024 + kg] = hbits(h1);
        }

        // ---- device-wide barrier: 8 split counters, release arrival ----
        __syncthreads();                       // CTA-wide happens-before
        if (tid == 0) {
            red_release(&g_ctr8[(g & 7) * 32]);
        }
        if (tid < 8) {
            const unsigned tgt = (unsigned)(l + 1) * 16u;
            while (*(volatile unsigned int*)&g_ctr8[tid * 32] < tgt) {
                __nanosleep(32);
            }
            __threadfence();                   // acquire for the 8 pollers
        }
        __syncthreads();
    }

    // ---- final h_n, c_n ----
    {
        const size_t base_hn = (size_t)Ll * Bz * Hh;
        const size_t base_cn = base_hn + (size_t)Bz * Hh;
        out[base_hn + (size_t)b_e * Hh + kg] = hst;
        out[base_cn + (size_t)b_e * Hh + kg] = cst;
    }
}

// ---------------------------------------------------------------------------
extern "C" void kernel_launch(void* const* d_in, const int* in_sizes, int n_in,
                              void* d_out, int out_size)
{
    const float* x    = (const float*)d_in[0];
    const void*  pa   = (const void*)d_in[1];
    // d_in[2] = mask (unused by the reference computation)
    const float* h0   = (const float*)d_in[3];
    const float* c0   = (const float*)d_in[4];
    const float* rule = (const float*)d_in[5];
    const float* toke = (const float*)d_in[6];
    const float* Wih  = (const float*)d_in[7];
    const float* Whh  = (const float*)d_in[8];
    const float* bih  = (const float*)d_in[9];
    const float* bhh  = (const float*)d_in[10];
    float* out = (float*)d_out;

    fused_proj<<<dim3(64, 4, 3), 256>>>(rule, toke, x, Wih, bih, bhh,
                                        (const int*)pa);
    prep_w<<<512, 256>>>(Whh);
    prep_h0<<<8, 256>>>(h0);

    cudaFuncSetAttribute(lstm_mma,
                         cudaFuncAttributeMaxDynamicSharedMemorySize,
                         SMEM_BYTES);
    lstm_mma<<<NCTA, TPB, SMEM_BYTES>>>(c0, pa, toke, Wih, out);
}